// round 1
// baseline (speedup 1.0000x reference)
#include <cuda_runtime.h>
#include <math_constants.h>

// CapsuleLinear with k-means routing, priors never materialized:
//   logits[n] = x_n . (W^T out_n)        (8-wide dot)
//   out       = W . (sum_n probs_n x_n)  (16x8 matvec)
// One CTA handles (b, 4 consecutive o). 128 threads, 9 rows each (1152 = 128*9),
// x rows live in registers for all 3 iterations and all 4 o's.

#define TPB   128
#define NWARP 4
#define ROWS  9
#define OPB   4
#define NB    64
#define NN    1152
#define NO    64
#define NL    16
#define NI    8
#define NITER 3
#define EPSV  1e-12f

__global__ __launch_bounds__(TPB) void caps_kernel(
    const float* __restrict__ x,     // [NB, NN, NI]
    const float* __restrict__ w,     // [NO, NL, NI]
    float* __restrict__ outbuf)      // [NB*NO*NL] out, then [NB*NO*NN] probs
{
    float* out_ptr   = outbuf;
    float* probs_ptr = outbuf + NB * NO * NL;

    const int tid  = threadIdx.x;
    const int lane = tid & 31;
    const int wid  = tid >> 5;
    const int b    = blockIdx.x / (NO / OPB);
    const int og   = blockIdx.x % (NO / OPB);

    __shared__ float sW[OPB][NL][NI];     // weights for the 4 o's of this block
    __shared__ float sredA[NWARP];        // per-warp max partials
    __shared__ float sredB[NWARP][NI + 1];// per-warp (sum, y[8]) partials
    __shared__ float sredC[NI + 1];       // finalized (sum, y[8])
    __shared__ float s_out[NL];           // centroid (warp0-private scratch)
    __shared__ float s_v[NI];             // v = W^T out_n (broadcast)
    __shared__ float s_s[NI];             // s = sum_n x_n (broadcast)
    __shared__ float s_invsum;            // softmax 1/sum (broadcast, last iter)

    // ---- load the 4 weight tiles (contiguous 512 floats) ----
    {
        const float* wsrc = w + og * OPB * NL * NI;
        for (int idx = tid; idx < OPB * NL * NI; idx += TPB)
            ((float*)sW)[idx] = wsrc[idx];
    }

    // ---- load this thread's 9 x rows into registers (float4 pairs) ----
    float xr[ROWS][NI];
    const float* xb = x + (size_t)b * NN * NI;
#pragma unroll
    for (int r = 0; r < ROWS; r++) {
        const float4* p = reinterpret_cast<const float4*>(xb + (tid + r * TPB) * NI);
        float4 a0 = p[0];
        float4 a1 = p[1];
        xr[r][0] = a0.x; xr[r][1] = a0.y; xr[r][2] = a0.z; xr[r][3] = a0.w;
        xr[r][4] = a1.x; xr[r][5] = a1.y; xr[r][6] = a1.z; xr[r][7] = a1.w;
    }

    // ---- s = sum over all n of x_n (8-vector block reduction) ----
    {
        float part[NI];
#pragma unroll
        for (int i = 0; i < NI; i++) {
            float acc = 0.f;
#pragma unroll
            for (int r = 0; r < ROWS; r++) acc += xr[r][i];
#pragma unroll
            for (int off = 16; off; off >>= 1)
                acc += __shfl_xor_sync(0xffffffffu, acc, off);
            part[i] = acc;
        }
        if (lane == 0) {
#pragma unroll
            for (int i = 0; i < NI; i++) sredB[wid][i] = part[i];
        }
    }
    __syncthreads();
    if (tid < NI) {
        float acc = 0.f;
#pragma unroll
        for (int wv = 0; wv < NWARP; wv++) acc += sredB[wv][tid];
        s_s[tid] = acc;
    }
    __syncthreads();

    // ---- loop over the 4 output capsules handled by this block ----
    for (int j = 0; j < OPB; j++) {
        const int o = og * OPB + j;

        // init centroid: out = W . (s / N)   (warp0 lanes < 16)
        if (wid == 0) {
            if (lane < NL) {
                float acc = 0.f;
#pragma unroll
                for (int i = 0; i < NI; i++) acc += sW[j][lane][i] * s_s[i];
                s_out[lane] = acc * (1.0f / NN);
            }
            __syncwarp();
        }

        float e[ROWS];

        for (int it = 0; it < NITER; it++) {
            // -- warp0: normalize centroid, v = W^T out_n --
            if (wid == 0) {
                float ol = (lane < NL) ? s_out[lane] : 0.f;
                float sq = ol * ol;
#pragma unroll
                for (int off = 16; off; off >>= 1)
                    sq += __shfl_xor_sync(0xffffffffu, sq, off);
                float innorm = 1.0f / fmaxf(sqrtf(sq), EPSV);
                if (lane < NI) {
                    float acc = 0.f;
#pragma unroll
                    for (int l = 0; l < NL; l++) acc += sW[j][l][lane] * s_out[l];
                    s_v[lane] = acc * innorm;
                }
            }
            __syncthreads();  // sync1: s_v visible to all

            // -- logits + local max --
            float v0 = s_v[0], v1 = s_v[1], v2 = s_v[2], v3 = s_v[3];
            float v4 = s_v[4], v5 = s_v[5], v6 = s_v[6], v7 = s_v[7];
            float lg[ROWS];
            float lmax = -CUDART_INF_F;
#pragma unroll
            for (int r = 0; r < ROWS; r++) {
                float acc = xr[r][0] * v0;
                acc = fmaf(xr[r][1], v1, acc);
                acc = fmaf(xr[r][2], v2, acc);
                acc = fmaf(xr[r][3], v3, acc);
                acc = fmaf(xr[r][4], v4, acc);
                acc = fmaf(xr[r][5], v5, acc);
                acc = fmaf(xr[r][6], v6, acc);
                acc = fmaf(xr[r][7], v7, acc);
                lg[r] = acc;
                lmax = fmaxf(lmax, acc);
            }
#pragma unroll
            for (int off = 16; off; off >>= 1)
                lmax = fmaxf(lmax, __shfl_xor_sync(0xffffffffu, lmax, off));
            if (lane == 0) sredA[wid] = lmax;
            __syncthreads();  // sync2: max partials visible

            float m = sredA[0];
#pragma unroll
            for (int wv = 1; wv < NWARP; wv++) m = fmaxf(m, sredA[wv]);

            // -- exp, partial sum and partial y --
            float psum = 0.f;
            float py[NI];
#pragma unroll
            for (int i = 0; i < NI; i++) py[i] = 0.f;
#pragma unroll
            for (int r = 0; r < ROWS; r++) {
                float ev = __expf(lg[r] - m);
                e[r] = ev;
                psum += ev;
#pragma unroll
                for (int i = 0; i < NI; i++) py[i] = fmaf(ev, xr[r][i], py[i]);
            }
#pragma unroll
            for (int off = 16; off; off >>= 1)
                psum += __shfl_xor_sync(0xffffffffu, psum, off);
#pragma unroll
            for (int i = 0; i < NI; i++) {
#pragma unroll
                for (int off = 16; off; off >>= 1)
                    py[i] += __shfl_xor_sync(0xffffffffu, py[i], off);
            }
            if (lane == 0) {
                sredB[wid][0] = psum;
#pragma unroll
                for (int i = 0; i < NI; i++) sredB[wid][1 + i] = py[i];
            }
            __syncthreads();  // sync3: (sum, y) partials visible

            // -- warp0: finalize sum & y, new centroid out = W.(y/sum) --
            if (wid == 0) {
                if (lane < NI + 1) {
                    float acc = sredB[0][lane];
#pragma unroll
                    for (int wv = 1; wv < NWARP; wv++) acc += sredB[wv][lane];
                    sredC[lane] = acc;
                }
                __syncwarp();
                float invs = 1.0f / sredC[0];
                if (lane < NL) {
                    float acc = 0.f;
#pragma unroll
                    for (int i = 0; i < NI; i++) acc += sW[j][lane][i] * sredC[1 + i];
                    s_out[lane] = acc * invs;
                }
                if (lane == 0) s_invsum = invs;
                __syncwarp();
            }

            if (it == NITER - 1) {
                __syncthreads();  // sync4: s_invsum visible
                const float invs = s_invsum;
                float* pbase = probs_ptr + ((size_t)b * NO + o) * NN;
#pragma unroll
                for (int r = 0; r < ROWS; r++)
                    pbase[tid + r * TPB] = e[r] * invs;
            }
        }

        // final centroid for this o (computed in last iteration by warp0)
        if (wid == 0 && lane < NL)
            out_ptr[((size_t)b * NO + o) * NL + lane] = s_out[lane];

        __syncthreads();  // protect shared scratch before next o
    }
}

extern "C" void kernel_launch(void* const* d_in, const int* in_sizes, int n_in,
                              void* d_out, int out_size) {
    const float* x = (const float*)d_in[0];   // [64,1152,8]
    const float* w = (const float*)d_in[1];   // [64,16,8]
    float* out = (float*)d_out;               // 65536 (out) + 4718592 (probs)
    (void)in_sizes; (void)n_in; (void)out_size;
    dim3 grid(NB * (NO / OPB));   // 64 * 16 = 1024 blocks
    caps_kernel<<<grid, TPB>>>(x, w, out);
}

// round 2
// speedup vs baseline: 1.8186x; 1.8186x over previous
#include <cuda_runtime.h>

// CapsuleLinear k-means routing, fully collapsed:
//   state = y (8-vector per o). v = G y / sqrt(y^T G y), G = W^T W.
//   logits_n = x_n . v ; e = exp(logits) (no max-shift needed, |logit|<~20)
//   y' = sum_n e_n x_n ; sum = sum_n e_n
//   final: out = (W y)/sum, probs = e/sum.
// Packed f32x2 FMA halves FFMA issue count. Split-scheme warp reduce: 14 shfl.

#define TPB   128
#define NWARP 4
#define ROWS  9
#define OPB   4
#define NB    64
#define NN    1152
#define NO    64
#define NL    16
#define NI    8
#define NITER 3

typedef unsigned long long u64;

__device__ __forceinline__ u64 pack2(float x, float y) {
    u64 r; asm("mov.b64 %0, {%1, %2};" : "=l"(r) : "f"(x), "f"(y)); return r;
}
__device__ __forceinline__ void unpack2(u64 v, float& x, float& y) {
    asm("mov.b64 {%0, %1}, %2;" : "=f"(x), "=f"(y) : "l"(v));
}
__device__ __forceinline__ u64 ffma2(u64 a, u64 b, u64 c) {
    u64 d; asm("fma.rn.f32x2 %0, %1, %2, %3;" : "=l"(d) : "l"(a), "l"(b), "l"(c)); return d;
}
__device__ __forceinline__ u64 fadd2(u64 a, u64 b) {
    u64 d; asm("add.rn.f32x2 %0, %1, %2;" : "=l"(d) : "l"(a), "l"(b)); return d;
}

// Reduce 8 values across the warp with 9 shfl. Returns warp-sum of component
// comp(lane); lanes 0..7 cover all 8 components.
__device__ __forceinline__ float warpReduce8(const float* v, int lane, int& comp) {
    const unsigned FM = 0xffffffffu;
    bool h1 = lane & 1;
    float a0 = (h1 ? v[4] : v[0]) + __shfl_xor_sync(FM, h1 ? v[0] : v[4], 1);
    float a1 = (h1 ? v[5] : v[1]) + __shfl_xor_sync(FM, h1 ? v[1] : v[5], 1);
    float a2 = (h1 ? v[6] : v[2]) + __shfl_xor_sync(FM, h1 ? v[2] : v[6], 1);
    float a3 = (h1 ? v[7] : v[3]) + __shfl_xor_sync(FM, h1 ? v[3] : v[7], 1);
    bool h2 = lane & 2;
    float b0 = (h2 ? a2 : a0) + __shfl_xor_sync(FM, h2 ? a0 : a2, 2);
    float b1 = (h2 ? a3 : a1) + __shfl_xor_sync(FM, h2 ? a1 : a3, 2);
    bool h4 = lane & 4;
    float c  = (h4 ? b1 : b0) + __shfl_xor_sync(FM, h4 ? b0 : b1, 4);
    c += __shfl_xor_sync(FM, c, 8);
    c += __shfl_xor_sync(FM, c, 16);
    comp = (lane & 1) * 4 + (lane & 2) + ((lane >> 2) & 1);
    return c;
}

__global__ __launch_bounds__(TPB, 4) void caps_kernel(
    const float* __restrict__ x,     // [NB, NN, NI]
    const float* __restrict__ w,     // [NO, NL, NI]
    float* __restrict__ outbuf)      // [NB*NO*NL] out, then [NB*NO*NN] probs
{
    float* out_ptr   = outbuf;
    float* probs_ptr = outbuf + NB * NO * NL;

    const int tid  = threadIdx.x;
    const int lane = tid & 31;
    const int wid  = tid >> 5;
    const int b    = blockIdx.x >> 4;
    const int og   = blockIdx.x & 15;

    __shared__ float sW[OPB][NL][NI];          // 2 KB
    __shared__ float sG[OPB][NI][NI];          // 1 KB (G = W^T W per o)
    __shared__ float sred[OPB][NWARP][NI + 1]; // per-warp (y[8], sum) partials
    __shared__ float s_s0[NI];                 // initial y (= sum_n x_n)
    __shared__ float s_v[OPB][NI];             // v per o
    __shared__ float sY[OPB][NI];              // final y per o
    __shared__ float s_invs[OPB];              // final 1/sum per o
    __shared__ float se[OPB * NN];             // 18 KB, staged e for probs

    // ---- x rows into registers (packed f32x2) ----
    u64 xr[ROWS][4];
    {
        const float4* xb4 = reinterpret_cast<const float4*>(x + (size_t)b * NN * NI);
#pragma unroll
        for (int r = 0; r < ROWS; r++) {
            int n = r * TPB + tid;
            float4 a0 = xb4[2 * n];
            float4 a1 = xb4[2 * n + 1];
            xr[r][0] = pack2(a0.x, a0.y); xr[r][1] = pack2(a0.z, a0.w);
            xr[r][2] = pack2(a1.x, a1.y); xr[r][3] = pack2(a1.z, a1.w);
        }
    }

    // ---- weights for this block's 4 o's ----
    {
        const float* wsrc = w + (size_t)og * OPB * NL * NI;
#pragma unroll
        for (int k = 0; k < 4; k++)
            ((float*)sW)[tid + k * TPB] = wsrc[tid + k * TPB];
    }
    __syncthreads();

    // ---- G = W^T W per o (256 entries, 2 per thread) ----
#pragma unroll
    for (int e = tid; e < OPB * NI * NI; e += TPB) {
        int o = e >> 6, i = (e >> 3) & 7, jj = e & 7;
        float acc = 0.f;
#pragma unroll
        for (int l = 0; l < NL; l++) acc += sW[o][l][i] * sW[o][l][jj];
        sG[o][i][jj] = acc;
    }

    // ---- s = sum_n x_n (per-warp partial) ----
    {
        u64 acc0 = xr[0][0], acc1 = xr[0][1], acc2 = xr[0][2], acc3 = xr[0][3];
#pragma unroll
        for (int r = 1; r < ROWS; r++) {
            acc0 = fadd2(acc0, xr[r][0]); acc1 = fadd2(acc1, xr[r][1]);
            acc2 = fadd2(acc2, xr[r][2]); acc3 = fadd2(acc3, xr[r][3]);
        }
        float sv[8];
        unpack2(acc0, sv[0], sv[1]); unpack2(acc1, sv[2], sv[3]);
        unpack2(acc2, sv[4], sv[5]); unpack2(acc3, sv[6], sv[7]);
        int comp; float red = warpReduce8(sv, lane, comp);
        if (lane < 8) sred[0][wid][comp] = red;
    }
    __syncthreads();

    if (tid < NI)
        s_s0[tid] = sred[0][0][tid] + sred[0][1][tid] + sred[0][2][tid] + sred[0][3][tid];

    // warp0 caches its G row
    float Gr[NI];
    if (wid == 0) {
        int o = lane >> 3, i = lane & 7;
#pragma unroll
        for (int j = 0; j < NI; j++) Gr[j] = sG[o][i][j];
    }
    __syncthreads();

    // ---- routing iterations ----
    for (int it = 0; it < NITER; ++it) {
        if (wid == 0) {
            const unsigned FM = 0xffffffffu;
            int o = lane >> 3, i = lane & 7;
            float yi;
            if (it == 0) yi = s_s0[i];
            else yi = sred[o][0][i] + sred[o][1][i] + sred[o][2][i] + sred[o][3][i];
            float g = 0.f;
            int gbase = lane & 24;
#pragma unroll
            for (int j = 0; j < NI; j++) {
                float yj = __shfl_sync(FM, yi, gbase | j);
                g = fmaf(Gr[j], yj, g);
            }
            float p = yi * g;
            p += __shfl_xor_sync(FM, p, 1);
            p += __shfl_xor_sync(FM, p, 2);
            p += __shfl_xor_sync(FM, p, 4);
            s_v[o][i] = g * rsqrtf(p);
        }
        __syncthreads();

        const bool last = (it == NITER - 1);
#pragma unroll
        for (int o = 0; o < OPB; o++) {
            const float4* vp = reinterpret_cast<const float4*>(s_v[o]);
            float4 vA = vp[0], vB = vp[1];
            u64 v0 = pack2(vA.x, vA.y), v1 = pack2(vA.z, vA.w);
            u64 v2 = pack2(vB.x, vB.y), v3 = pack2(vB.z, vB.w);
            u64 py0 = 0ull, py1 = 0ull, py2 = 0ull, py3 = 0ull;
            float psum = 0.f;
#pragma unroll
            for (int r = 0; r < ROWS; r++) {
                u64 acc = ffma2(xr[r][0], v0, 0ull);
                acc = ffma2(xr[r][1], v1, acc);
                acc = ffma2(xr[r][2], v2, acc);
                acc = ffma2(xr[r][3], v3, acc);
                float lx, ly; unpack2(acc, lx, ly);
                float ev = __expf(lx + ly);
                psum += ev;
                if (last) se[o * NN + r * TPB + tid] = ev;
                u64 ev2 = pack2(ev, ev);
                py0 = ffma2(ev2, xr[r][0], py0);
                py1 = ffma2(ev2, xr[r][1], py1);
                py2 = ffma2(ev2, xr[r][2], py2);
                py3 = ffma2(ev2, xr[r][3], py3);
            }
            float pv[8];
            unpack2(py0, pv[0], pv[1]); unpack2(py1, pv[2], pv[3]);
            unpack2(py2, pv[4], pv[5]); unpack2(py3, pv[6], pv[7]);
            int comp; float red = warpReduce8(pv, lane, comp);
            const unsigned FM = 0xffffffffu;
            psum += __shfl_xor_sync(FM, psum, 1);
            psum += __shfl_xor_sync(FM, psum, 2);
            psum += __shfl_xor_sync(FM, psum, 4);
            psum += __shfl_xor_sync(FM, psum, 8);
            psum += __shfl_xor_sync(FM, psum, 16);
            if (lane < 8) sred[o][wid][comp] = red;
            if (lane == 0) sred[o][wid][NI] = psum;
        }
        __syncthreads();
    }

    // ---- finalize y, 1/sum ----
    if (tid < OPB * (NI + 1)) {                 // 36 threads
        int o = tid / (NI + 1), cmp = tid % (NI + 1);
        float acc = sred[o][0][cmp] + sred[o][1][cmp] + sred[o][2][cmp] + sred[o][3][cmp];
        if (cmp < NI) sY[o][cmp] = acc;
        else          s_invs[o] = 1.0f / acc;
    }
    __syncthreads();

    // ---- out = (W y) / sum ----
    if (tid < OPB * NL) {                        // 64 threads
        int o = tid >> 4, l = tid & 15;
        float acc = 0.f;
#pragma unroll
        for (int i = 0; i < NI; i++) acc = fmaf(sW[o][l][i], sY[o][i], acc);
        out_ptr[((size_t)b * NO + og * OPB + o) * NL + l] = acc * s_invs[o];
    }

    // ---- probs = e / sum ----
#pragma unroll
    for (int o = 0; o < OPB; o++) {
        float inv = s_invs[o];
        float* pb = probs_ptr + ((size_t)b * NO + og * OPB + o) * NN;
        const float4* sp = reinterpret_cast<const float4*>(se + o * NN);
        float4 q0 = sp[tid];
        q0.x *= inv; q0.y *= inv; q0.z *= inv; q0.w *= inv;
        reinterpret_cast<float4*>(pb)[tid] = q0;
        float4 q1 = sp[TPB + tid];
        q1.x *= inv; q1.y *= inv; q1.z *= inv; q1.w *= inv;
        reinterpret_cast<float4*>(pb)[TPB + tid] = q1;
        pb[8 * TPB + tid] = se[o * NN + 8 * TPB + tid] * inv;
    }
}

extern "C" void kernel_launch(void* const* d_in, const int* in_sizes, int n_in,
                              void* d_out, int out_size) {
    const float* x = (const float*)d_in[0];   // [64,1152,8]
    const float* w = (const float*)d_in[1];   // [64,16,8]
    float* out = (float*)d_out;
    (void)in_sizes; (void)n_in; (void)out_size;
    dim3 grid(NB * (NO / OPB));               // 1024 blocks
    caps_kernel<<<grid, TPB>>>(x, w, out);
}